// round 8
// baseline (speedup 1.0000x reference)
#include <cuda_runtime.h>
#include <math.h>

// Preisach hysteresis, fully fused single-kernel version (R7).
//   state row j = prefix of +1 of length c_j, then -1 (within lower triangle).
//   up-step h:   rows with x[j] < h  -> c_j = j+1
//   down-step h: all rows            -> c_j = min(c_j, K), K = #{k: x[k] <= h}
//   b[t] = (sum_j (2*P_j(c_j) - RowTot_j)) / 32896 * scale + offset
// One launch, 125 co-resident CTAs, grid-wide spin barriers between phases:
//   P1: row prefix sums (blocks 0-15) + per-chunk meta/compose (blocks 16-95)
//   P2: chunk-function scan -> entry states + total (block 0)
//   P3: one warp per output step (125*16 = 2000 warps)

#define NN 256
#define TT 2000
#define CHUNK 25
#define NCHUNK 80
#define NB 125
#define QSCALE 8192.0f

__device__ int g_Li[NN * (NN + 1) / 2 + NN];       // row-local prefix sums (quantized)
__device__ int g_RowTotI[NN];
__device__ int g_meta[TT];                          // -1 up, -2 flat, else K (down)
__device__ __align__(16) int g_fvT[NN * NCHUNK];    // [row][chunk] transfer functions
__device__ int g_centry[NCHUNK * NN];               // [chunk][row] entry states
__device__ int g_TotalI;

__device__ unsigned g_barflag = 0;   // monotonically increasing across replays
__device__ int      g_barcnt  = 0;   // self-resetting arrival counter

__device__ __forceinline__ float xval(int i) {
    // replicate jnp.linspace(0,1,256) in f32: i * fl(1/255), endpoint exact
    return (i == NN - 1) ? 1.0f : (float)i * (1.0f / 255.0f);
}
__device__ __forceinline__ float softplusf(float v) {
    return fmaxf(v, 0.0f) + log1pf(expf(-fabsf(v)));
}

// Grid-wide barrier. All NB CTAs are co-resident (NB <= #SMs), so spinning is
// safe. 'base' is the flag value sampled at kernel entry (thread 0), making
// the monotonic flag correct across graph replays. Counter self-resets.
__device__ __forceinline__ void grid_sync(unsigned base, unsigned gen) {
    __syncthreads();
    if (threadIdx.x == 0) {
        __threadfence();                       // publish this CTA's phase writes
        int v = atomicAdd(&g_barcnt, 1);
        if (v == NB - 1) {
            g_barcnt = 0;                      // reset before release
            __threadfence();
            *(volatile unsigned*)&g_barflag = base + gen;   // release
        } else {
            while ((int)(*(volatile unsigned*)&g_barflag - base) < (int)gen)
                __nanosleep(32);
        }
        __threadfence();
    }
    __syncthreads();
}

__global__ void __launch_bounds__(512, 1)
fused_all(const float* __restrict__ raw, const float* __restrict__ h,
          const float* __restrict__ offset, const float* __restrict__ scale,
          float* __restrict__ out) {
    __shared__ int   sm[CHUNK];
    __shared__ float shh[CHUNK];
    __shared__ int   sred[16];

    unsigned base = 0;
    if (threadIdx.x == 0) base = *(volatile unsigned*)&g_barflag;

    int bx  = blockIdx.x;
    int tid = threadIdx.x;

    // ================= Phase 1 =================
    if (bx < 16) {
        // per-row prefix sums of softplus(raw), one warp per row, MLP=8
        int warp = (bx * 512 + tid) >> 5;     // row 0..255
        int lane = tid & 31;
        int j  = warp;
        int sj = j * (j + 1) / 2;
        int oj = sj + j;
        int n  = j + 1;

        int basee = lane * 8;
        float v[8];
        #pragma unroll
        for (int k = 0; k < 8; k++) {
            int idx = basee + k;
            v[k] = (idx < n) ? raw[sj + idx] : 0.0f;
        }
        int loc[8];
        int run = 0;
        #pragma unroll
        for (int k = 0; k < 8; k++) {
            int idx = basee + k;
            int q = (idx < n) ? __float2int_rn(softplusf(v[k]) * QSCALE) : 0;
            run += q;
            loc[k] = run;
        }
        int excl = run;
        #pragma unroll
        for (int d = 1; d < 32; d <<= 1) {
            int t = __shfl_up_sync(0xffffffffu, excl, d);
            if (lane >= d) excl += t;
        }
        excl -= run;

        if (lane == 0) g_Li[oj] = 0;
        #pragma unroll
        for (int k = 0; k < 8; k++) {
            int idx = basee + k;
            if (idx < n) g_Li[oj + 1 + idx] = excl + loc[k];
        }
        if (lane == 31) g_RowTotI[j] = excl + run;
    } else if (bx < 96) {
        // per-step meta + per-(chunk,row) transfer compose
        int ci = bx - 16;
        int j  = tid;
        int t0 = ci * CHUNK;

        if (j < CHUNK) {
            int t = t0 + j;
            float hp = (t == 0) ? 0.0f : h[t - 1];
            float hc = h[t];
            int m;
            if (hc > hp) {
                m = -1;
            } else if (hc < hp) {
                int K = 0;
                #pragma unroll 8
                for (int k = 0; k < NN; k++) K += (xval(k) <= hc) ? 1 : 0;
                m = K;
            } else {
                m = -2;
            }
            sm[j] = m; shh[j] = hc;
            g_meta[t] = m;
        }
        __syncthreads();
        if (j < NN) {
            float xj = xval(j);
            bool isC = false;
            int vv = 0, m = 511;
            #pragma unroll
            for (int s = 0; s < CHUNK; s++) {
                int mt = sm[s];
                if (mt == -1) {
                    if (xj < shh[s]) { isC = true; vv = j + 1; }
                } else if (mt >= 0) {
                    if (isC) vv = min(vv, mt); else m = min(m, mt);
                }
            }
            g_fvT[j * NCHUNK + ci] = isC ? (512 + vv) : m;
        }
    }

    grid_sync(base, 1);

    // ================= Phase 2 (block 0) =================
    if (bx == 0) {
        int j = tid;
        if (j < NN) {
            const int4* fv = reinterpret_cast<const int4*>(&g_fvT[j * NCHUNK]);
            int f[NCHUNK];
            #pragma unroll
            for (int b = 0; b < NCHUNK / 4; b++) {
                int4 t4 = fv[b];
                f[4 * b + 0] = t4.x; f[4 * b + 1] = t4.y;
                f[4 * b + 2] = t4.z; f[4 * b + 3] = t4.w;
            }
            int c = 0;
            #pragma unroll
            for (int i = 0; i < NCHUNK; i++) {
                g_centry[i * NN + j] = c;
                int fs = f[i];
                c = (fs >= 512) ? (fs - 512) : min(c, fs);
            }
        }
        int rt = (j < NN) ? g_RowTotI[j] : 0;
        int ws = __reduce_add_sync(0xffffffffu, rt);
        if ((j & 31) == 0) sred[j >> 5] = ws;
        __syncthreads();
        if (j == 0) {
            int s = 0;
            #pragma unroll
            for (int w = 0; w < 16; w++) s += sred[w];
            g_TotalI = s;
        }
    }

    grid_sync(base, 2);

    // ================= Phase 3: one warp per output step =================
    {
        int wid  = tid >> 5;
        int lane = tid & 31;
        int t  = bx * 16 + wid;                 // 0..1999 exactly
        int ci = t / CHUNK;
        int t0 = ci * CHUNK;
        int nst = t - t0 + 1;                   // 1..25 steps to replay

        int   myMt = -2;
        float myH  = 0.0f;
        if (lane < CHUNK) { myMt = g_meta[t0 + lane]; myH = h[t0 + lane]; }

        int   c[8], oj[8];
        float xq[8];
        #pragma unroll
        for (int q = 0; q < 8; q++) {
            int j = lane + 32 * q;
            oj[q] = j * (j + 3) / 2;
            xq[q] = xval(j);
            c[q]  = g_centry[ci * NN + j];
        }

        for (int u = 0; u < nst; u++) {
            int   mt = __shfl_sync(0xffffffffu, myMt, u);
            float hc = __shfl_sync(0xffffffffu, myH, u);
            if (mt == -1) {
                #pragma unroll
                for (int q = 0; q < 8; q++) {
                    int j = lane + 32 * q;
                    if (xq[q] < hc) c[q] = j + 1;
                }
            } else if (mt >= 0) {
                #pragma unroll
                for (int q = 0; q < 8; q++) c[q] = min(c[q], mt);
            }
        }

        int rv[8];
        #pragma unroll
        for (int q = 0; q < 8; q++) rv[q] = g_Li[oj[q] + c[q]];

        int s8 = ((rv[0] + rv[1]) + (rv[2] + rv[3])) +
                 ((rv[4] + rv[5]) + (rv[6] + rv[7]));
        int tot = __reduce_add_sync(0xffffffffu, s8);

        if (lane == 0) {
            float numer = (float)(2 * tot - g_TotalI) * (1.0f / QSCALE);
            out[t] = numer * (1.0f / 32896.0f) * scale[0] + offset[0];
        }
    }
}

extern "C" void kernel_launch(void* const* d_in, const int* in_sizes, int n_in,
                              void* d_out, int out_size) {
    const float* h      = (const float*)d_in[0];
    const float* raw    = (const float*)d_in[1];
    const float* offset = (const float*)d_in[2];
    const float* scale  = (const float*)d_in[3];
    float* out = (float*)d_out;

    fused_all<<<NB, 512>>>(raw, h, offset, scale, out);
}

// round 9
// speedup vs baseline: 1.1915x; 1.1915x over previous
#include <cuda_runtime.h>
#include <math.h>

// Preisach hysteresis (R8): 2 kernels, no grid barrier.
//   state row j = prefix of +1 of length c_j, then -1 (within lower triangle).
//   up-step h:   rows with x[j] < h  -> c_j = j+1
//   down-step h: all rows            -> c_j = min(c_j, K), K = #{k: x[k] <= h}
//   b[t] = (sum_j (2*P_j(c_j) - RowTot_j)) / 32896 * scale + offset
// K1: row prefix sums (blocks 0-15) + meta (binary-search K) + chunk compose
//     (blocks 16-95).
// K2: per-CTA redundant entry-scan of its <=2 needed chunks (512 pairs = 512
//     threads) + redundant total reduce, then one warp per output step.

#define NN 256
#define TT 2000
#define CHUNK 25
#define NCHUNK 80
#define QSCALE 8192.0f

__device__ int g_Li[NN * (NN + 1) / 2 + NN];      // row-local prefix sums (quantized)
__device__ int g_RowTotI[NN];
__device__ int g_meta[TT];                         // -1 up, -2 flat, else K (down)
__device__ __align__(16) int g_fvT[NN * NCHUNK];   // [row][chunk] transfer functions

__device__ __forceinline__ float xval(int i) {
    // replicate jnp.linspace(0,1,256) in f32: i * fl(1/255), endpoint exact
    return (i == NN - 1) ? 1.0f : (float)i * (1.0f / 255.0f);
}
__device__ __forceinline__ float softplusf(float v) {
    return fmaxf(v, 0.0f) + log1pf(expf(-fabsf(v)));
}
// K = #{k in [0,256): xval(k) <= hc}. xval is weakly monotone in k, so the
// predicate is a prefix property -> branchless binary search, identical ties.
// (hc < 1 always on down-steps, so K <= 255 and s0=128 suffices.)
__device__ __forceinline__ int count_le(float hc) {
    int K = 0;
    #pragma unroll
    for (int s = 128; s > 0; s >>= 1) {
        int cand = K + s;
        if (xval(cand - 1) <= hc) K = cand;
    }
    return K;
}

// ---------------- Kernel 1 ----------------
__global__ void __launch_bounds__(512)
k1_build(const float* __restrict__ raw, const float* __restrict__ h) {
    int tid = threadIdx.x;
    if (blockIdx.x < 16) {
        // per-row prefix sums of softplus(raw), one warp per row, MLP=8
        int warp = (blockIdx.x * 512 + tid) >> 5;   // row 0..255
        int lane = tid & 31;
        int j  = warp;
        int sj = j * (j + 1) / 2;
        int oj = sj + j;
        int n  = j + 1;

        int base = lane * 8;
        float v[8];
        #pragma unroll
        for (int k = 0; k < 8; k++) {
            int idx = base + k;
            v[k] = (idx < n) ? raw[sj + idx] : 0.0f;
        }
        int loc[8];
        int run = 0;
        #pragma unroll
        for (int k = 0; k < 8; k++) {
            int idx = base + k;
            int q = (idx < n) ? __float2int_rn(softplusf(v[k]) * QSCALE) : 0;
            run += q;
            loc[k] = run;
        }
        int excl = run;
        #pragma unroll
        for (int d = 1; d < 32; d <<= 1) {
            int t = __shfl_up_sync(0xffffffffu, excl, d);
            if (lane >= d) excl += t;
        }
        excl -= run;

        if (lane == 0) g_Li[oj] = 0;
        #pragma unroll
        for (int k = 0; k < 8; k++) {
            int idx = base + k;
            if (idx < n) g_Li[oj + 1 + idx] = excl + loc[k];
        }
        if (lane == 31) g_RowTotI[j] = excl + run;
    } else {
        // per-step meta (binary-search K) + per-(chunk,row) compose
        __shared__ int   sm[CHUNK];
        __shared__ float shh[CHUNK];
        int ci = blockIdx.x - 16;
        int j  = tid;
        int t0 = ci * CHUNK;

        if (j < CHUNK) {
            int t = t0 + j;
            float hp = (t == 0) ? 0.0f : h[t - 1];
            float hc = h[t];
            int m;
            if (hc > hp)       m = -1;
            else if (hc < hp)  m = count_le(hc);
            else               m = -2;
            sm[j] = m; shh[j] = hc;
            g_meta[t] = m;
        }
        __syncthreads();
        if (j < NN) {
            float xj = xval(j);
            bool isC = false;
            int vv = 0, m = 511;
            #pragma unroll
            for (int s = 0; s < CHUNK; s++) {
                int mt = sm[s];
                if (mt == -1) {
                    if (xj < shh[s]) { isC = true; vv = j + 1; }
                } else if (mt >= 0) {
                    if (isC) vv = min(vv, mt); else m = min(m, mt);
                }
            }
            g_fvT[j * NCHUNK + ci] = isC ? (512 + vv) : m;
        }
    }
}

// ---------------- Kernel 2 ----------------
// 125 CTAs x 512 threads. CTA handles steps [bx*16, bx*16+16), which span at
// most 2 chunks ci0/ci1. Threads 0-255 scan entries for (ci0, row tid),
// threads 256-511 for (ci1, row tid-256). Then 16 warps emit 16 outputs.
__global__ void __launch_bounds__(512)
k2_emit(const float* __restrict__ h, const float* __restrict__ offset,
        const float* __restrict__ scale, float* __restrict__ out) {
    __shared__ int entry[512];
    __shared__ int stot[16];

    int tid = threadIdx.x;
    int bx  = blockIdx.x;
    int blockBase = bx * 16;
    int ci0 = blockBase / CHUNK;
    int ci1 = (blockBase + 15) / CHUNK;

    // --- redundant entry scan for this CTA's <=2 chunks ---
    {
        int j    = tid & 255;
        int cilm = (tid < 256) ? ci0 : ci1;
        const int4* fv = reinterpret_cast<const int4*>(&g_fvT[j * NCHUNK]);
        int c = 0;
        #pragma unroll
        for (int g = 0; g < 4; g++) {                 // 4 groups x 5 int4 (MLP=5)
            int4 a0 = fv[g * 5 + 0], a1 = fv[g * 5 + 1], a2 = fv[g * 5 + 2],
                 a3 = fv[g * 5 + 3], a4 = fv[g * 5 + 4];
            int vals[20] = {a0.x,a0.y,a0.z,a0.w, a1.x,a1.y,a1.z,a1.w,
                            a2.x,a2.y,a2.z,a2.w, a3.x,a3.y,a3.z,a3.w,
                            a4.x,a4.y,a4.z,a4.w};
            #pragma unroll
            for (int k = 0; k < 20; k++) {
                int i  = g * 20 + k;
                int fs = vals[k];
                int nc = (fs >= 512) ? (fs - 512) : min(c, fs);
                c = (i < cilm) ? nc : c;
            }
        }
        entry[tid] = c;

        // redundant total reduce (each row counted once by threads 0-255)
        int rt = (tid < 256) ? g_RowTotI[j] : 0;
        int ws = __reduce_add_sync(0xffffffffu, rt);
        if ((tid & 31) == 0) stot[tid >> 5] = ws;
    }
    __syncthreads();

    int totalI = 0;
    #pragma unroll
    for (int w = 0; w < 16; w++) totalI += stot[w];

    // --- one warp per output step ---
    int wid  = tid >> 5;
    int lane = tid & 31;
    int t   = blockBase + wid;
    int ci  = t / CHUNK;
    int t0  = ci * CHUNK;
    int nst = t - t0 + 1;                  // 1..25 steps to replay
    int eb  = (ci == ci0) ? 0 : 256;

    int   myMt = -2;
    float myH  = 0.0f;
    if (lane < CHUNK) { myMt = g_meta[t0 + lane]; myH = h[t0 + lane]; }

    int   c[8], oj[8];
    float xq[8];
    #pragma unroll
    for (int q = 0; q < 8; q++) {
        int j = lane + 32 * q;
        oj[q] = j * (j + 3) / 2;
        xq[q] = xval(j);
        c[q]  = entry[eb + j];
    }

    for (int u = 0; u < nst; u++) {
        int   mt = __shfl_sync(0xffffffffu, myMt, u);
        float hc = __shfl_sync(0xffffffffu, myH, u);
        if (mt == -1) {
            #pragma unroll
            for (int q = 0; q < 8; q++) {
                int j = lane + 32 * q;
                if (xq[q] < hc) c[q] = j + 1;
            }
        } else if (mt >= 0) {
            #pragma unroll
            for (int q = 0; q < 8; q++) c[q] = min(c[q], mt);
        }
    }

    int rv[8];
    #pragma unroll
    for (int q = 0; q < 8; q++) rv[q] = g_Li[oj[q] + c[q]];   // 8 parallel LDG

    int s8 = ((rv[0] + rv[1]) + (rv[2] + rv[3])) +
             ((rv[4] + rv[5]) + (rv[6] + rv[7]));
    int tot = __reduce_add_sync(0xffffffffu, s8);

    if (lane == 0) {
        float numer = (float)(2 * tot - totalI) * (1.0f / QSCALE);
        out[t] = numer * (1.0f / 32896.0f) * scale[0] + offset[0];
    }
}

extern "C" void kernel_launch(void* const* d_in, const int* in_sizes, int n_in,
                              void* d_out, int out_size) {
    const float* h      = (const float*)d_in[0];
    const float* raw    = (const float*)d_in[1];
    const float* offset = (const float*)d_in[2];
    const float* scale  = (const float*)d_in[3];
    float* out = (float*)d_out;

    k1_build<<<96, 512>>>(raw, h);
    k2_emit<<<125, 512>>>(h, offset, scale, out);
}

// round 12
// speedup vs baseline: 1.4485x; 1.2157x over previous
#include <cuda_runtime.h>
#include <math.h>

// Preisach hysteresis (R9): 2 kernels.
//   state row j = prefix of +1 of length c_j, then -1 (within lower triangle).
//   up-step h:   rows with x[j] < h  -> c_j = j+1
//   down-step h: all rows            -> c_j = min(c_j, K), K = #{k: x[k] <= h}
//   b[t] = (sum_j (2*P_j(c_j) - RowTot_j)) / 32896 * scale + offset
// Function encode: SET(v) = 512+v, MIN(m) = m (m<=511).
// K1: row prefix sums (blocks 0-15); meta + per-step WITHIN-CHUNK prefix
//     functions g_F[t][j] + per-chunk functions g_fv[ci][j] (blocks 16-95).
// K2: per-CTA entry scan (coalesced, 256 threads, derive ci1 entry from ci0
//     with one extra compose), then one warp per step: apply g_F to entry,
//     one Li lookup per row-group, REDUX.

#define NN 256
#define TT 2000
#define CHUNK 25
#define NCHUNK 80
#define QSCALE 8192.0f

__device__ int g_Li[NN * (NN + 1) / 2 + NN];   // row-local prefix sums (quantized)
__device__ int g_RowTotI[NN];
__device__ int g_fv[NCHUNK * NN];               // [chunk][row] chunk functions
__device__ int g_F[TT * NN];                    // [t][row] within-chunk prefix functions

__device__ __forceinline__ float xval(int i) {
    // replicate jnp.linspace(0,1,256) in f32: i * fl(1/255), endpoint exact
    return (i == NN - 1) ? 1.0f : (float)i * (1.0f / 255.0f);
}
__device__ __forceinline__ float softplusf(float v) {
    return fmaxf(v, 0.0f) + log1pf(expf(-fabsf(v)));
}
// K = #{k in [0,256): xval(k) <= hc}; xval weakly monotone -> branchless
// binary search with the identical '<=' predicate (hc<1 on down-steps).
__device__ __forceinline__ int count_le(float hc) {
    int K = 0;
    #pragma unroll
    for (int s = 128; s > 0; s >>= 1) {
        int cand = K + s;
        if (xval(cand - 1) <= hc) K = cand;
    }
    return K;
}

// ---------------- Kernel 1 ----------------
__global__ void __launch_bounds__(512)
k1_build(const float* __restrict__ raw, const float* __restrict__ h) {
    int tid = threadIdx.x;
    if (blockIdx.x < 16) {
        // per-row prefix sums of softplus(raw), one warp per row, MLP=8
        int warp = (blockIdx.x * 512 + tid) >> 5;   // row 0..255
        int lane = tid & 31;
        int j  = warp;
        int sj = j * (j + 1) / 2;
        int oj = sj + j;
        int n  = j + 1;

        int base = lane * 8;
        float v[8];
        #pragma unroll
        for (int k = 0; k < 8; k++) {
            int idx = base + k;
            v[k] = (idx < n) ? raw[sj + idx] : 0.0f;
        }
        int loc[8];
        int run = 0;
        #pragma unroll
        for (int k = 0; k < 8; k++) {
            int idx = base + k;
            int q = (idx < n) ? __float2int_rn(softplusf(v[k]) * QSCALE) : 0;
            run += q;
            loc[k] = run;
        }
        int excl = run;
        #pragma unroll
        for (int d = 1; d < 32; d <<= 1) {
            int t = __shfl_up_sync(0xffffffffu, excl, d);
            if (lane >= d) excl += t;
        }
        excl -= run;

        if (lane == 0) g_Li[oj] = 0;
        #pragma unroll
        for (int k = 0; k < 8; k++) {
            int idx = base + k;
            if (idx < n) g_Li[oj + 1 + idx] = excl + loc[k];
        }
        if (lane == 31) g_RowTotI[j] = excl + run;
    } else {
        // per-step meta + per-(step,row) prefix functions + chunk function
        __shared__ int   sm[CHUNK];
        __shared__ float shh[CHUNK];
        int ci = blockIdx.x - 16;
        int j  = tid;
        int t0 = ci * CHUNK;

        if (j < CHUNK) {
            int t = t0 + j;
            float hp = (t == 0) ? 0.0f : h[t - 1];
            float hc = h[t];
            int m;
            if (hc > hp)       m = -1;
            else if (hc < hp)  m = count_le(hc);
            else               m = -2;
            sm[j] = m; shh[j] = hc;
        }
        __syncthreads();
        if (j < NN) {
            float xj = xval(j);
            bool isC = false;
            int vv = 0, m = 511;
            #pragma unroll
            for (int s = 0; s < CHUNK; s++) {
                int mt = sm[s];
                if (mt == -1) {
                    if (xj < shh[s]) { isC = true; vv = j + 1; }
                } else if (mt >= 0) {
                    if (isC) vv = min(vv, mt); else m = min(m, mt);
                }
                g_F[(t0 + s) * NN + j] = isC ? (512 + vv) : m;  // coalesced
            }
            g_fv[ci * NN + j] = isC ? (512 + vv) : m;
        }
    }
}

// ---------------- Kernel 2 ----------------
// 125 CTAs x 512 threads. CTA handles steps [bx*16, bx*16+16), spanning
// chunks ci0..ci1 (ci1 <= ci0+1). Threads 0-255 scan entry(ci0) with
// coalesced loads, derive entry(ci1) via one extra compose. 16 warps emit.
__global__ void __launch_bounds__(512)
k2_emit(const float* __restrict__ offset, const float* __restrict__ scale,
        float* __restrict__ out) {
    __shared__ int entry[512];
    __shared__ int stot[16];

    int tid = threadIdx.x;
    int bx  = blockIdx.x;
    int blockBase = bx * 16;
    int ci0 = blockBase / CHUNK;
    int ci1 = (blockBase + 15) / CHUNK;

    if (tid < 256) {
        int j = tid;
        int c = 0;
        #pragma unroll
        for (int i = 0; i < NCHUNK; i++) {
            int fs = g_fv[i * NN + j];                  // coalesced LDG.32
            int nc = (fs >= 512) ? (fs - 512) : min(c, fs);
            c = (i < ci0) ? nc : c;                     // ci0 uniform per CTA
        }
        entry[j] = c;
        int c1 = c;
        if (ci1 > ci0) {
            int fs = g_fv[ci0 * NN + j];
            c1 = (fs >= 512) ? (fs - 512) : min(c, fs);
        }
        entry[256 + j] = c1;
    }
    // redundant total reduce (rows counted once by threads 0-255)
    {
        int rt = (tid < 256) ? g_RowTotI[tid] : 0;
        int ws = __reduce_add_sync(0xffffffffu, rt);
        if ((tid & 31) == 0) stot[tid >> 5] = ws;
    }
    __syncthreads();

    int totalI = 0;
    #pragma unroll
    for (int w = 0; w < 16; w++) totalI += stot[w];

    // --- one warp per output step: apply stored prefix function ---
    int wid  = tid >> 5;
    int lane = tid & 31;
    int t  = blockBase + wid;
    int ci = t / CHUNK;
    int eb = (ci == ci0) ? 0 : 256;

    int c[8], oj[8];
    #pragma unroll
    for (int q = 0; q < 8; q++) {
        int j = lane + 32 * q;
        oj[q] = j * (j + 3) / 2;
        int F = g_F[t * NN + j];                        // coalesced LDG.32
        int e = entry[eb + j];
        c[q] = (F >= 512) ? (F - 512) : min(e, F);
    }

    int rv[8];
    #pragma unroll
    for (int q = 0; q < 8; q++) rv[q] = g_Li[oj[q] + c[q]];   // 8 parallel LDG

    int s8 = ((rv[0] + rv[1]) + (rv[2] + rv[3])) +
             ((rv[4] + rv[5]) + (rv[6] + rv[7]));
    int tot = __reduce_add_sync(0xffffffffu, s8);

    if (lane == 0) {
        float numer = (float)(2 * tot - totalI) * (1.0f / QSCALE);
        out[t] = numer * (1.0f / 32896.0f) * scale[0] + offset[0];
    }
}

extern "C" void kernel_launch(void* const* d_in, const int* in_sizes, int n_in,
                              void* d_out, int out_size) {
    const float* h      = (const float*)d_in[0];
    const float* raw    = (const float*)d_in[1];
    const float* offset = (const float*)d_in[2];
    const float* scale  = (const float*)d_in[3];
    float* out = (float*)d_out;

    k1_build<<<96, 512>>>(raw, h);
    k2_emit<<<125, 512>>>(offset, scale, out);
}

// round 13
// speedup vs baseline: 1.4521x; 1.0025x over previous
#include <cuda_runtime.h>
#include <math.h>

// Preisach hysteresis (R12): 2 kernels.
//   state row j = prefix of +1 of length c_j, then -1 (within lower triangle).
//   up-step h:   rows with x[j] < h  -> c_j = j+1
//   down-step h: all rows            -> c_j = min(c_j, K), K = #{k: x[k] <= h}
//   b[t] = (sum_j (2*P_j(c_j) - RowTot_j)) / 32896 * scale + offset
// Function encode: SET(v) = 512+v, MIN(m) = m (m <= 511; MIN(511) = identity).
// K1: row prefix sums (blocks 0-15); per-step within-chunk prefix functions
//     g_F[t][j] + per-chunk functions g_fv[ci][j] (blocks 16-95).
// K2: split entry scan (threads 0-255: value over chunks [0,40); 256-511:
//     composed function over [40,80)), emit loads hoisted above the scan,
//     one warp per step, one Li gather + REDUX.

#define NN 256
#define TT 2000
#define CHUNK 25
#define NCHUNK 80
#define QSCALE 8192.0f

__device__ int g_Li[NN * (NN + 1) / 2 + NN];   // row-local prefix sums (quantized)
__device__ int g_RowTotI[NN];
__device__ int g_fv[NCHUNK * NN];               // [chunk][row] chunk functions
__device__ int g_F[TT * NN];                    // [t][row] within-chunk prefix functions

__device__ __forceinline__ float xval(int i) {
    // replicate jnp.linspace(0,1,256) in f32: i * fl(1/255), endpoint exact
    return (i == NN - 1) ? 1.0f : (float)i * (1.0f / 255.0f);
}
__device__ __forceinline__ float softplusf(float v) {
    return fmaxf(v, 0.0f) + log1pf(expf(-fabsf(v)));
}
// K = #{k in [0,256): xval(k) <= hc}; xval weakly monotone -> branchless
// binary search with the identical '<=' predicate (hc<1 on down-steps).
__device__ __forceinline__ int count_le(float hc) {
    int K = 0;
    #pragma unroll
    for (int s = 128; s > 0; s >>= 1) {
        int cand = K + s;
        if (xval(cand - 1) <= hc) K = cand;
    }
    return K;
}
// apply encoded function to a state
__device__ __forceinline__ int fapply(int enc, int c) {
    return (enc >= 512) ? (enc - 512) : min(c, enc);
}

// ---------------- Kernel 1 ----------------
__global__ void __launch_bounds__(512)
k1_build(const float* __restrict__ raw, const float* __restrict__ h) {
    int tid = threadIdx.x;
    if (blockIdx.x < 16) {
        // per-row prefix sums of softplus(raw), one warp per row, MLP=8
        int warp = (blockIdx.x * 512 + tid) >> 5;   // row 0..255
        int lane = tid & 31;
        int j  = warp;
        int sj = j * (j + 1) / 2;
        int oj = sj + j;
        int n  = j + 1;

        int base = lane * 8;
        float v[8];
        #pragma unroll
        for (int k = 0; k < 8; k++) {
            int idx = base + k;
            v[k] = (idx < n) ? raw[sj + idx] : 0.0f;
        }
        int loc[8];
        int run = 0;
        #pragma unroll
        for (int k = 0; k < 8; k++) {
            int idx = base + k;
            int q = (idx < n) ? __float2int_rn(softplusf(v[k]) * QSCALE) : 0;
            run += q;
            loc[k] = run;
        }
        int excl = run;
        #pragma unroll
        for (int d = 1; d < 32; d <<= 1) {
            int t = __shfl_up_sync(0xffffffffu, excl, d);
            if (lane >= d) excl += t;
        }
        excl -= run;

        if (lane == 0) g_Li[oj] = 0;
        #pragma unroll
        for (int k = 0; k < 8; k++) {
            int idx = base + k;
            if (idx < n) g_Li[oj + 1 + idx] = excl + loc[k];
        }
        if (lane == 31) g_RowTotI[j] = excl + run;
    } else {
        // per-step meta + per-(step,row) prefix functions + chunk function
        __shared__ int   sm[CHUNK];
        __shared__ float shh[CHUNK];
        int ci = blockIdx.x - 16;
        int j  = tid;
        int t0 = ci * CHUNK;

        if (j < CHUNK) {
            int t = t0 + j;
            float hp = (t == 0) ? 0.0f : h[t - 1];
            float hc = h[t];
            int m;
            if (hc > hp)       m = -1;
            else if (hc < hp)  m = count_le(hc);
            else               m = -2;
            sm[j] = m; shh[j] = hc;
        }
        __syncthreads();
        if (j < NN) {
            float xj = xval(j);
            bool isC = false;
            int vv = 0, m = 511;
            #pragma unroll
            for (int s = 0; s < CHUNK; s++) {
                int mt = sm[s];
                if (mt == -1) {
                    if (xj < shh[s]) { isC = true; vv = j + 1; }
                } else if (mt >= 0) {
                    if (isC) vv = min(vv, mt); else m = min(m, mt);
                }
                g_F[(t0 + s) * NN + j] = isC ? (512 + vv) : m;  // coalesced
            }
            g_fv[ci * NN + j] = isC ? (512 + vv) : m;
        }
    }
}

// ---------------- Kernel 2 ----------------
// 125 CTAs x 512 threads. CTA bx handles steps [bx*16, bx*16+16), chunks
// ci0..ci1 (ci1 <= ci0+1). All emit loads hoisted above the scan.
__global__ void __launch_bounds__(512)
k2_emit(const float* __restrict__ offset, const float* __restrict__ scale,
        float* __restrict__ out) {
    __shared__ int sA[256];    // value after chunks [0, min(ci0,40))
    __shared__ int sB[256];    // encoded function over chunks [40, ci0)
    __shared__ int stot[16];

    int tid = threadIdx.x;
    int bx  = blockIdx.x;
    int blockBase = bx * 16;
    int ci0 = blockBase / CHUNK;
    int ci1 = (blockBase + 15) / CHUNK;

    // ---- emit-side prefetch (independent of scan) ----
    int wid  = tid >> 5;
    int lane = tid & 31;
    int t  = blockBase + wid;
    int ci = t / CHUNK;
    int Fq[8], fc0[8], oj[8];
    #pragma unroll
    for (int q = 0; q < 8; q++) {
        int j = lane + 32 * q;
        oj[q]  = j * (j + 3) / 2;
        Fq[q]  = g_F[t * NN + j];          // coalesced
        fc0[q] = g_fv[ci0 * NN + j];       // coalesced (for ci1 entry compose)
    }
    int jrow = tid & 255;
    int rt = (tid < 256) ? g_RowTotI[jrow] : 0;

    // ---- split entry scan, full register prefetch (MLP=40) ----
    {
        int base = (tid < 256) ? 0 : 40;
        int fv[40];
        #pragma unroll
        for (int i = 0; i < 40; i++) fv[i] = g_fv[(base + i) * NN + jrow];

        if (tid < 256) {
            int c = 0;
            #pragma unroll
            for (int i = 0; i < 40; i++) {
                int fs = fv[i];
                int nc = fapply(fs, c);
                c = (i < ci0) ? nc : c;
            }
            sA[jrow] = c;
        } else {
            int enc = 511;                  // identity MIN
            #pragma unroll
            for (int i = 0; i < 40; i++) {
                int fs = fv[i];
                int ne = (fs >= 512) ? fs
                       : ((enc >= 512) ? (512 + min(enc - 512, fs))
                                       : min(enc, fs));
                enc = (40 + i < ci0) ? ne : enc;
            }
            sB[jrow] = enc;
        }
    }
    // redundant total reduce (rows counted once by threads 0-255)
    {
        int ws = __reduce_add_sync(0xffffffffu, rt);
        if ((tid & 31) == 0) stot[tid >> 5] = ws;
    }
    __syncthreads();

    int totalI = 0;
    #pragma unroll
    for (int w = 0; w < 16; w++) totalI += stot[w];

    // ---- one warp per step: entries from smem + stored prefix function ----
    int c[8];
    #pragma unroll
    for (int q = 0; q < 8; q++) {
        int j  = lane + 32 * q;
        int e  = fapply(sB[j], sA[j]);       // entry(ci0)
        if (ci != ci0) e = fapply(fc0[q], e); // entry(ci0+1)
        c[q] = fapply(Fq[q], e);
    }

    int rv[8];
    #pragma unroll
    for (int q = 0; q < 8; q++) rv[q] = g_Li[oj[q] + c[q]];   // 8 parallel LDG

    int s8 = ((rv[0] + rv[1]) + (rv[2] + rv[3])) +
             ((rv[4] + rv[5]) + (rv[6] + rv[7]));
    int tot = __reduce_add_sync(0xffffffffu, s8);

    if (lane == 0) {
        float numer = (float)(2 * tot - totalI) * (1.0f / QSCALE);
        out[t] = numer * (1.0f / 32896.0f) * scale[0] + offset[0];
    }
}

extern "C" void kernel_launch(void* const* d_in, const int* in_sizes, int n_in,
                              void* d_out, int out_size) {
    const float* h      = (const float*)d_in[0];
    const float* raw    = (const float*)d_in[1];
    const float* offset = (const float*)d_in[2];
    const float* scale  = (const float*)d_in[3];
    float* out = (float*)d_out;

    k1_build<<<96, 512>>>(raw, h);
    k2_emit<<<125, 512>>>(offset, scale, out);
}